// round 1
// baseline (speedup 1.0000x reference)
#include <cuda_runtime.h>
#include <math.h>

#define BB  8
#define LL  512
#define KK  16
#define EE  32
#define NHH 64
#define GG  192

// -------- scratch (static device globals; no runtime allocation) --------
__device__ float g_q[BB*LL*EE];
__device__ float g_k[BB*LL*EE];
__device__ float g_S[BB*LL*LL];      // scores / sqrt(32)
__device__ int   g_bcnt[BB*KK];
__device__ int   g_bidx[BB*KK*LL];   // per (b,c) ordered list of positions
__device__ float g_M2[GG*KK];        // W_ih @ Wo   (192 x 16)
__device__ float g_cc[GG];           // W_ih @ bo + b_ih
__device__ float g_GI[BB*LL*GG];     // precomputed input gates

// -------- kernel 1: key_emb + Q/K projection --------
__global__ void k_prep(const float* __restrict__ ts,
                       const float* __restrict__ Wl, const float* __restrict__ bl,
                       const float* __restrict__ Wp, const float* __restrict__ bp,
                       const float* __restrict__ Wq, const float* __restrict__ bq,
                       const float* __restrict__ Wk, const float* __restrict__ bk) {
    __shared__ float sWq[EE*EE], sWk[EE*EE], sWp[EE], sbp[EE], sbq[EE], sbk[EE];
    __shared__ float sWl, sbl;
    int tid = threadIdx.x;
    for (int i = tid; i < EE*EE; i += blockDim.x) { sWq[i] = Wq[i]; sWk[i] = Wk[i]; }
    if (tid < EE-1) { sWp[tid] = Wp[tid]; sbp[tid] = bp[tid]; }
    if (tid < EE)   { sbq[tid] = bq[tid]; sbk[tid] = bk[tid]; }
    if (tid == 0)   { sWl = Wl[0]; sbl = bl[0]; }
    __syncthreads();
    int idx = blockIdx.x * blockDim.x + tid;      // (b*L + l)
    float t = ts[idx];
    float ke[EE];
    ke[0] = t * sWl + sbl;
    #pragma unroll
    for (int i = 1; i < EE; i++) ke[i] = sinf(t * sWp[i-1] + sbp[i-1]);
    #pragma unroll 4
    for (int e = 0; e < EE; e++) {
        float aq = sbq[e], ak = sbk[e];
        #pragma unroll
        for (int j = 0; j < EE; j++) {
            aq += sWq[e*EE+j] * ke[j];
            ak += sWk[e*EE+j] * ke[j];
        }
        g_q[idx*EE+e] = aq;
        g_k[idx*EE+e] = ak;
    }
}

// -------- kernel 2: per-(b,category) ordered position buckets --------
__global__ void k_bucket(const int* __restrict__ mark, const float* __restrict__ npm) {
    int b = blockIdx.x, c = threadIdx.x;   // 16 threads/block
    int pos = 0;
    for (int k = 0; k < LL; k++) {
        int   mk = mark[b*LL+k];
        float np = npm[b*LL+k];            // non_pad_mask[b,k,0]
        if (mk == c+1 && np > 0.f) { g_bidx[(b*KK+c)*LL + pos] = k; pos++; }
    }
    g_bcnt[b*KK+c] = pos;
}

// -------- kernel 3: fold Wo into W_ih:  M2 = W_ih@Wo, cc = W_ih@bo + b_ih --------
__global__ void k_m2(const float* __restrict__ W_ih, const float* __restrict__ Wo,
                     const float* __restrict__ b_ih, const float* __restrict__ bo) {
    int g = threadIdx.x;  // 192 threads
    float wrow[NHH];
    #pragma unroll
    for (int o = 0; o < NHH; o++) wrow[o] = W_ih[g*NHH+o];
    float cc = b_ih[g];
    #pragma unroll
    for (int o = 0; o < NHH; o++) cc += wrow[o] * bo[o];
    g_cc[g] = cc;
    for (int c = 0; c < KK; c++) {
        float a = 0.f;
        #pragma unroll
        for (int o = 0; o < NHH; o++) a += wrow[o] * Wo[o*KK+c];
        g_M2[g*KK+c] = a;
    }
}

// -------- kernel 4: scores = q @ k^T / sqrt(32)  (tiled, smem) --------
__global__ void k_scores() {
    __shared__ float q_s[32*33];
    __shared__ float k_s[64*33];
    int tid = threadIdx.x;                 // 256 threads
    int b = blockIdx.y;
    int qbase = blockIdx.x * 32;
    for (int i = tid; i < 32*EE; i += 256) {
        int r = i >> 5, e = i & 31;
        q_s[r*33+e] = g_q[(b*LL + qbase + r)*EE + e];
    }
    int ql = tid >> 3, kg = tid & 7;
    const float sc = 0.17677669529663687f; // 1/sqrt(32)
    for (int kt = 0; kt < 8; kt++) {
        __syncthreads();
        for (int i = tid; i < 64*EE; i += 256) {
            int r = i >> 5, e = i & 31;
            k_s[r*33+e] = g_k[(b*LL + kt*64 + r)*EE + e];
        }
        __syncthreads();
        float acc[8];
        #pragma unroll
        for (int i = 0; i < 8; i++) acc[i] = 0.f;
        #pragma unroll
        for (int e = 0; e < EE; e++) {
            float qv = q_s[ql*33+e];
            #pragma unroll
            for (int i = 0; i < 8; i++) acc[i] += qv * k_s[(kg*8+i)*33+e];
        }
        float* so = &g_S[((size_t)(b*LL) + qbase + ql)*LL + kt*64 + kg*8];
        #pragma unroll
        for (int i = 0; i < 8; i++) so[i] = acc[i] * sc;
    }
}

// -------- kernel 5: bucketed softmax + fused (Wo,W_ih) epilogue -> GI --------
__global__ void k_att(const float* __restrict__ val) {
    __shared__ float val_s[LL];
    __shared__ int   cnt_s[KK];
    __shared__ float x_s[32*KK];
    __shared__ float M2_s[GG*17];          // padded stride 17 (conflict-free)
    __shared__ float cc_s[GG];
    int tid = threadIdx.x;                 // 512 threads = 16 warps
    int b = blockIdx.y;
    int qbase = blockIdx.x * 32;
    for (int i = tid; i < LL; i += 512) val_s[i] = val[b*LL+i];
    if (tid < KK) cnt_s[tid] = g_bcnt[b*KK+tid];
    for (int i = tid; i < GG*KK; i += 512) {
        int g = i >> 4, c = i & 15;
        M2_s[g*17+c] = g_M2[i];
    }
    if (tid < GG) cc_s[tid] = g_cc[tid];
    __syncthreads();

    int wid = tid >> 5, lane = tid & 31;
    for (int task = wid; task < 32*KK; task += 16) {
        int ql = task >> 4, c = task & 15;
        int q = qbase + ql;
        int cnt = cnt_s[c];
        // online softmax over this category's bucket.
        // logit = s if k <= q+1 else 0 (W_OFF=1): future-masked positions with
        // matching mark still contribute exp(0) — matches reference exactly.
        float m = -1e30f, se = 0.f, sv = 0.f;
        for (int i = lane; i < cnt; i += 32) {
            int   kk = g_bidx[(b*KK+c)*LL + i];
            float s  = g_S[((size_t)(b*LL) + q)*LL + kk];
            float lg = (kk <= q+1) ? s : 0.f;
            float v  = val_s[kk];
            float nm = fmaxf(m, lg);
            float ea = __expf(m - nm), eb = __expf(lg - nm);
            se = se*ea + eb;
            sv = sv*ea + eb*v;
            m = nm;
        }
        #pragma unroll
        for (int off = 16; off > 0; off >>= 1) {
            float mo  = __shfl_xor_sync(0xffffffffu, m,  off);
            float seo = __shfl_xor_sync(0xffffffffu, se, off);
            float svo = __shfl_xor_sync(0xffffffffu, sv, off);
            float nm = fmaxf(m, mo);
            float ea = __expf(m - nm), eb = __expf(mo - nm);
            se = se*ea + seo*eb;
            sv = sv*ea + svo*eb;
            m = nm;
        }
        if (lane == 0) x_s[ql*KK+c] = (se > 0.f) ? sv/se : 0.f;
    }
    __syncthreads();

    // GI[b, q, g] = cc[g] + sum_c M2[g][c] * x[q][c]
    for (int o = tid; o < 32*GG; o += 512) {
        int ql = o / GG, g = o % GG;
        float acc = cc_s[g];
        #pragma unroll
        for (int c = 0; c < KK; c++) acc += M2_s[g*17+c] * x_s[ql*KK+c];
        g_GI[((size_t)(b*LL) + qbase + ql)*GG + g] = acc;
    }
}

// -------- kernel 6: GRU scan — one block per independent batch chain --------
__global__ void __launch_bounds__(GG) k_gru(const float* __restrict__ W_hh,
                                            const float* __restrict__ b_hh,
                                            float* __restrict__ out) {
    int b = blockIdx.x, t = threadIdx.x;   // 192 threads: one per gate row
    __shared__ __align__(16) float h_s[NHH];
    __shared__ float gh_s[GG];
    float w[NHH];
    #pragma unroll
    for (int j = 0; j < NHH; j++) w[j] = W_hh[t*NHH + j];
    float bh = b_hh[t];
    if (t < NHH) h_s[t] = 0.f;

    float g0 = 0.f, g1 = 0.f, g2 = 0.f;    // current-step input gates
    if (t < NHH) {
        const float* gp = g_GI + (size_t)b*LL*GG;
        g0 = gp[t]; g1 = gp[t+NHH]; g2 = gp[t+2*NHH];
    }
    __syncthreads();

    for (int l = 0; l < LL; l++) {
        // prefetch next step's input gates early (L2 latency hides under matvec)
        float n0 = 0.f, n1 = 0.f, n2 = 0.f;
        if (t < NHH && l+1 < LL) {
            const float* gp = g_GI + ((size_t)b*LL + l + 1)*GG;
            n0 = gp[t]; n1 = gp[t+NHH]; n2 = gp[t+2*NHH];
        }
        // gh[t] = W_hh[t,:] . h  (weights in registers, 4 accumulator chains)
        float a0 = bh, a1 = 0.f, a2 = 0.f, a3 = 0.f;
        const float4* h4 = (const float4*)h_s;
        #pragma unroll
        for (int j4 = 0; j4 < NHH/4; j4++) {
            float4 hv = h4[j4];
            a0 += w[4*j4+0]*hv.x;
            a1 += w[4*j4+1]*hv.y;
            a2 += w[4*j4+2]*hv.z;
            a3 += w[4*j4+3]*hv.w;
        }
        gh_s[t] = (a0+a1) + (a2+a3);
        __syncthreads();
        if (t < NHH) {
            float hr = gh_s[t], hz = gh_s[t+NHH], hn = gh_s[t+2*NHH];
            float r = 1.f/(1.f + __expf(-(g0 + hr)));
            float z = 1.f/(1.f + __expf(-(g1 + hz)));
            float pre = g2 + r*hn;
            float cp = fminf(fmaxf(pre, -15.f), 15.f);
            float e2 = __expf(2.f*cp);
            float n  = (e2 - 1.f)/(e2 + 1.f);      // tanh
            float hnew = (1.f - z)*n + z*h_s[t];
            out[((size_t)b*LL + l)*NHH + t] = hnew;
            h_s[t] = hnew;
            g0 = n0; g1 = n1; g2 = n2;
        }
        __syncthreads();
    }
}

// -------- launch --------
extern "C" void kernel_launch(void* const* d_in, const int* in_sizes, int n_in,
                              void* d_out, int out_size) {
    const float* ts   = (const float*)d_in[0];
    const float* val  = (const float*)d_in[1];
    const int*   mark = (const int*)  d_in[2];
    const float* npm  = (const float*)d_in[3];
    const float* Wl   = (const float*)d_in[4];
    const float* bl   = (const float*)d_in[5];
    const float* Wp   = (const float*)d_in[6];
    const float* bp   = (const float*)d_in[7];
    const float* Wq   = (const float*)d_in[8];
    const float* bq   = (const float*)d_in[9];
    const float* Wk   = (const float*)d_in[10];
    const float* bk   = (const float*)d_in[11];
    const float* Wo   = (const float*)d_in[12];
    const float* bo   = (const float*)d_in[13];
    const float* W_ih = (const float*)d_in[14];
    const float* W_hh = (const float*)d_in[15];
    const float* b_ih = (const float*)d_in[16];
    const float* b_hh = (const float*)d_in[17];
    float* out = (float*)d_out;

    k_prep  <<<32, 128>>>(ts, Wl, bl, Wp, bp, Wq, bq, Wk, bk);
    k_bucket<<<8, 16>>>(mark, npm);
    k_m2    <<<1, 192>>>(W_ih, Wo, b_ih, bo);
    k_scores<<<dim3(16,8), 256>>>();
    k_att   <<<dim3(16,8), 512>>>(val);
    k_gru   <<<8, 192>>>(W_hh, b_hh, out);
}